// round 10
// baseline (speedup 1.0000x reference)
#include <cuda_runtime.h>
#include <cuda_fp16.h>
#include <cstdint>

#define CC 128  // channel width
#define XS 36   // padded Xs row stride for f32x2 GEMM

// ---------------------------------------------------------------------------
// Static scratch (no allocations allowed). Offsets in floats/ints.
// N0=200000, N1=50000, N2=12500; E0=3.2M, E1=800K, E2=200K. Row = 128 floats.
// g buffers are fp16 now (half the bytes) but keep their fp32-sized slots.
// ---------------------------------------------------------------------------
__device__ float g_scratch[112600000];  // ~450 MB

#define OFF_G0     0UL
#define OFF_T0     25600000UL
#define OFF_E0     51200000UL
#define OFF_G1     76800000UL
#define OFF_T1     83200000UL
#define OFF_E1     89600000UL
#define OFF_X1     96000000UL
#define OFF_G2     102400000UL
#define OFF_T2     104000000UL
#define OFF_X2     105600000UL
#define OFF_INV0   107200000UL
#define OFF_INV1   107400000UL
#define OFF_INV2   107450000UL
#define OFF_RP0    107500000UL
#define OFF_FILL0  107750000UL
#define OFF_RP1    107950000UL
#define OFF_FILL1  108010000UL
#define OFF_RP2    108060000UL
#define OFF_FILL2  108075000UL
#define OFF_ESRC0  108090000UL
#define OFF_ESRC1  111290000UL
#define OFF_ESRC2  112090000UL
#define OFF_BSUM   112400000UL

// ---------------------------------------------------------------------------
// f32x2 packed-math helpers
// ---------------------------------------------------------------------------
__device__ __forceinline__ void fma2(unsigned long long& d,
                                     unsigned long long a, unsigned long long b) {
    asm("fma.rn.f32x2 %0, %1, %2, %0;" : "+l"(d) : "l"(a), "l"(b));
}
__device__ __forceinline__ unsigned long long bcast2(float x) {
    unsigned long long r;
    asm("mov.b64 %0, {%1, %1};" : "=l"(r) : "f"(x));
    return r;
}
union U64F2 { unsigned long long u; float2 f; };

// ---------------------------------------------------------------------------
// Setup kernels
// ---------------------------------------------------------------------------
__global__ void zero_i(int* __restrict__ p, int n) {
    int i = blockIdx.x * blockDim.x + threadIdx.x;
    if (i < n) p[i] = 0;
}
__global__ void zero_f(float* __restrict__ p, int n) {
    int i = blockIdx.x * blockDim.x + threadIdx.x;
    if (i < n) p[i] = 0.0f;
}
__global__ void deg_count(const int* __restrict__ dst, int* __restrict__ cnt, int E) {
    int i = blockIdx.x * blockDim.x + threadIdx.x;
    if (i < E) atomicAdd(&cnt[dst[i]], 1);
}
__global__ void inv_from_cnt(const int* __restrict__ cnt, float* __restrict__ inv, int n) {
    int i = blockIdx.x * blockDim.x + threadIdx.x;
    if (i < n) inv[i] = rsqrtf((float)(cnt[i] + 1));
}

__global__ void scan_block(const int* __restrict__ cnt, int* __restrict__ rp,
                           int* __restrict__ bsum, int n) {
    __shared__ int wsums[32];
    const int t = threadIdx.x;
    int i = blockIdx.x * 1024 + t;
    int v = (i < n) ? cnt[i] : 0;
    int x = v;
    #pragma unroll
    for (int o = 1; o < 32; o <<= 1) {
        int y = __shfl_up_sync(0xffffffffu, x, o);
        if ((t & 31) >= o) x += y;
    }
    if ((t & 31) == 31) wsums[t >> 5] = x;
    __syncthreads();
    if (t < 32) {
        int w = wsums[t];
        #pragma unroll
        for (int o = 1; o < 32; o <<= 1) {
            int y = __shfl_up_sync(0xffffffffu, w, o);
            if (t >= o) w += y;
        }
        wsums[t] = w;
    }
    __syncthreads();
    int incl = x + ((t >= 32) ? wsums[(t >> 5) - 1] : 0);
    if (i < n) rp[i + 1] = incl;
    if (t == 1023) bsum[blockIdx.x] = incl;
}
__global__ void scan_sums(int* __restrict__ bsum, int nb) {
    __shared__ int wsums[8];
    const int t = threadIdx.x;  // 256 threads
    int v = (t < nb) ? bsum[t] : 0;
    int x = v;
    #pragma unroll
    for (int o = 1; o < 32; o <<= 1) {
        int y = __shfl_up_sync(0xffffffffu, x, o);
        if ((t & 31) >= o) x += y;
    }
    if ((t & 31) == 31) wsums[t >> 5] = x;
    __syncthreads();
    if (t < 32) {
        int w = (t < 8) ? wsums[t] : 0;
        #pragma unroll
        for (int o = 1; o < 8; o <<= 1) {
            int y = __shfl_up_sync(0xffffffffu, w, o);
            if (t >= o) w += y;
        }
        if (t < 8) wsums[t] = w;
    }
    __syncthreads();
    int incl = x + ((t >= 32) ? wsums[(t >> 5) - 1] : 0);
    if (t < nb) bsum[t] = incl - v;
}
__global__ void scan_add(const int* __restrict__ bsum, int* __restrict__ rp, int n) {
    int i = blockIdx.x * blockDim.x + threadIdx.x;
    if (i == 0) rp[0] = 0;
    if (i < n) rp[i + 1] += bsum[i >> 10];
}
__global__ void csr_fill(const int* __restrict__ src, const int* __restrict__ dst,
                         const int* __restrict__ rp, int* __restrict__ fill,
                         int* __restrict__ esrc, int E) {
    int e = blockIdx.x * blockDim.x + threadIdx.x;
    if (e >= E) return;
    int d = dst[e];
    int pos = rp[d] + atomicAdd(&fill[d], 1);
    esrc[pos] = src[e];
}

// ---------------------------------------------------------------------------
// f32x2 GEMM:
//   out[i][c] = epi( sum_k X(i,k) * W[k][c] )
//   X(i,k) = (k < Ka) ? xa[(gatherA ? gatherA[i] : i)][k] : xb[i][k-Ka]
//   epi: * inv[i] if inv; + bias[c], relu if requested.
// Output: fp32 to gf, OR fp16 to gh (exactly one non-null).
// Tile: 128 rows x 128 cols, 256 threads. Thread = 8 rows x 8 cols (4 pairs).
// ---------------------------------------------------------------------------
__global__ void __launch_bounds__(256)
gcn_gemm(const float* __restrict__ xa, const int* __restrict__ gatherA, int Ka,
         const float* __restrict__ xb, int Kb,
         const float* __restrict__ W, const float* __restrict__ inv,
         const float* __restrict__ bias, int do_relu,
         float* __restrict__ gf, __half* __restrict__ gh, int n)
{
    __shared__ float Ws[32 * CC];    // 16 KB
    __shared__ float Xs[128 * XS];   // 18 KB
    const int K = Ka + Kb;
    const int tid = threadIdx.x;
    const int cg = tid & 15;         // 8-col group
    const int rg = tid >> 4;         // 0..15; rows rg + 16*i
    const int row0 = blockIdx.x * 128;

    unsigned long long acc[8][4];
    #pragma unroll
    for (int i = 0; i < 8; ++i)
        #pragma unroll
        for (int j = 0; j < 4; ++j) acc[i][j] = 0ULL;

    for (int kk = 0; kk < K; kk += 32) {
        int kc = K - kk; if (kc > 32) kc = 32;
        const int kc4 = kc >> 2;
        for (int idx = tid; idx < kc * 32; idx += 256) {
            int k = idx >> 5, c4 = idx & 31;
            ((float4*)Ws)[k * 32 + c4] = ((const float4*)(W + (size_t)(kk + k) * CC))[c4];
        }
        for (int idx = tid; idx < 128 * kc4; idx += 256) {
            int r = idx / kc4, k4 = idx - r * kc4;
            int row = row0 + r;
            float4 v = make_float4(0.f, 0.f, 0.f, 0.f);
            if (row < n) {
                int kg = kk + k4 * 4;
                if (kg < Ka) {
                    int ra = gatherA ? __ldg(&gatherA[row]) : row;
                    v = *(const float4*)(xa + (size_t)ra * Ka + kg);
                } else {
                    v = *(const float4*)(xb + (size_t)row * Kb + (kg - Ka));
                }
            }
            *(float4*)(Xs + r * XS + k4 * 4) = v;
        }
        __syncthreads();
        for (int k4 = 0; k4 < kc4; ++k4) {
            float4 xv[8];
            #pragma unroll
            for (int i = 0; i < 8; ++i)
                xv[i] = *(const float4*)(Xs + (rg + 16 * i) * XS + k4 * 4);
            #pragma unroll
            for (int k = 0; k < 4; ++k) {
                const float* wrow = Ws + (k4 * 4 + k) * CC + cg * 8;
                ulonglong2 w01 = *(const ulonglong2*)(wrow);
                ulonglong2 w23 = *(const ulonglong2*)(wrow + 4);
                #pragma unroll
                for (int i = 0; i < 8; ++i) {
                    float xs = (k == 0) ? xv[i].x : (k == 1) ? xv[i].y
                             : (k == 2) ? xv[i].z : xv[i].w;
                    unsigned long long xb2 = bcast2(xs);
                    fma2(acc[i][0], xb2, w01.x);
                    fma2(acc[i][1], xb2, w01.y);
                    fma2(acc[i][2], xb2, w23.x);
                    fma2(acc[i][3], xb2, w23.y);
                }
            }
        }
        __syncthreads();
    }
    #pragma unroll
    for (int i = 0; i < 8; ++i) {
        int row = row0 + rg + 16 * i;
        if (row >= n) continue;
        float s = inv ? inv[row] : 1.0f;
        U64F2 p0, p1, p2, p3;
        p0.u = acc[i][0]; p1.u = acc[i][1]; p2.u = acc[i][2]; p3.u = acc[i][3];
        float4 v0 = make_float4(p0.f.x * s, p0.f.y * s, p1.f.x * s, p1.f.y * s);
        float4 v1 = make_float4(p2.f.x * s, p2.f.y * s, p3.f.x * s, p3.f.y * s);
        if (bias) {
            float4 b0 = *(const float4*)(bias + cg * 8);
            float4 b1 = *(const float4*)(bias + cg * 8 + 4);
            v0.x += b0.x; v0.y += b0.y; v0.z += b0.z; v0.w += b0.w;
            v1.x += b1.x; v1.y += b1.y; v1.z += b1.z; v1.w += b1.w;
        }
        if (do_relu) {
            v0.x = fmaxf(v0.x, 0.f); v0.y = fmaxf(v0.y, 0.f);
            v0.z = fmaxf(v0.z, 0.f); v0.w = fmaxf(v0.w, 0.f);
            v1.x = fmaxf(v1.x, 0.f); v1.y = fmaxf(v1.y, 0.f);
            v1.z = fmaxf(v1.z, 0.f); v1.w = fmaxf(v1.w, 0.f);
        }
        if (gh) {
            __half2 h0 = __floats2half2_rn(v0.x, v0.y);
            __half2 h1 = __floats2half2_rn(v0.z, v0.w);
            __half2 h2 = __floats2half2_rn(v1.x, v1.y);
            __half2 h3 = __floats2half2_rn(v1.z, v1.w);
            uint4 pk;
            pk.x = *(uint32_t*)&h0; pk.y = *(uint32_t*)&h1;
            pk.z = *(uint32_t*)&h2; pk.w = *(uint32_t*)&h3;
            *(uint4*)(gh + (size_t)row * CC + cg * 8) = pk;
        } else {
            float* op = gf + (size_t)row * CC + cg * 8;
            *(float4*)(op) = v0;
            *(float4*)(op + 4) = v1;
        }
    }
}

// ---------------------------------------------------------------------------
// CSR gather + finalize (+ optional fused max-pool and/or fused output head):
//   a = relu(inv[d] * (g[d] + sum_{e: dst=d} g[src[e]]) + bias)
// g is fp16 (half the gather bytes); accumulation in fp32.
// One warp per node; 4 channels (uint2 of half2) per lane; 8-deep MLP unroll.
// ---------------------------------------------------------------------------
__device__ __forceinline__ float4 h4_to_f4(uint2 r) {
    __half2 h0 = *(__half2*)&r.x;
    __half2 h1 = *(__half2*)&r.y;
    float2 f0 = __half22float2(h0);
    float2 f1 = __half22float2(h1);
    return make_float4(f0.x, f0.y, f1.x, f1.y);
}

__global__ void csr_gather_relu(const int* __restrict__ rp, const int* __restrict__ esrc,
                                const __half* __restrict__ g, const float* __restrict__ inv,
                                const float* __restrict__ bias, float* __restrict__ y,
                                const int* __restrict__ pool_cl, float* __restrict__ pool_out,
                                const float* __restrict__ head_w, const float* __restrict__ head_b,
                                float* __restrict__ head_out, int n)
{
    int node = (blockIdx.x * blockDim.x + threadIdx.x) >> 5;
    int lane = threadIdx.x & 31;
    if (node >= n) return;
    int beg = __ldg(&rp[node]);
    int end = __ldg(&rp[node + 1]);

    const int co = lane * 4;  // 4 channels per lane
    float4 a = h4_to_f4(*(const uint2*)(g + (size_t)node * CC + co));  // self loop
    int j = beg;
    for (; j + 8 <= end; j += 8) {
        int s0 = __ldcs(&esrc[j + 0]);
        int s1 = __ldcs(&esrc[j + 1]);
        int s2 = __ldcs(&esrc[j + 2]);
        int s3 = __ldcs(&esrc[j + 3]);
        int s4 = __ldcs(&esrc[j + 4]);
        int s5 = __ldcs(&esrc[j + 5]);
        int s6 = __ldcs(&esrc[j + 6]);
        int s7 = __ldcs(&esrc[j + 7]);
        uint2 r0 = *(const uint2*)(g + (size_t)s0 * CC + co);
        uint2 r1 = *(const uint2*)(g + (size_t)s1 * CC + co);
        uint2 r2 = *(const uint2*)(g + (size_t)s2 * CC + co);
        uint2 r3 = *(const uint2*)(g + (size_t)s3 * CC + co);
        uint2 r4 = *(const uint2*)(g + (size_t)s4 * CC + co);
        uint2 r5 = *(const uint2*)(g + (size_t)s5 * CC + co);
        uint2 r6 = *(const uint2*)(g + (size_t)s6 * CC + co);
        uint2 r7 = *(const uint2*)(g + (size_t)s7 * CC + co);
        float4 v0 = h4_to_f4(r0), v1 = h4_to_f4(r1);
        float4 v2 = h4_to_f4(r2), v3 = h4_to_f4(r3);
        float4 v4 = h4_to_f4(r4), v5 = h4_to_f4(r5);
        float4 v6 = h4_to_f4(r6), v7 = h4_to_f4(r7);
        a.x += (v0.x + v1.x) + (v2.x + v3.x) + (v4.x + v5.x) + (v6.x + v7.x);
        a.y += (v0.y + v1.y) + (v2.y + v3.y) + (v4.y + v5.y) + (v6.y + v7.y);
        a.z += (v0.z + v1.z) + (v2.z + v3.z) + (v4.z + v5.z) + (v6.z + v7.z);
        a.w += (v0.w + v1.w) + (v2.w + v3.w) + (v4.w + v5.w) + (v6.w + v7.w);
    }
    for (; j < end; ++j) {
        int s = __ldcs(&esrc[j]);
        float4 v = h4_to_f4(*(const uint2*)(g + (size_t)s * CC + co));
        a.x += v.x; a.y += v.y; a.z += v.z; a.w += v.w;
    }
    float s = __ldg(&inv[node]);
    float4 b = ((const float4*)bias)[lane];
    a.x = fmaxf(a.x * s + b.x, 0.f);
    a.y = fmaxf(a.y * s + b.y, 0.f);
    a.z = fmaxf(a.z * s + b.z, 0.f);
    a.w = fmaxf(a.w * s + b.w, 0.f);

    if (y) ((float4*)(y + (size_t)node * CC))[lane] = a;

    if (pool_out) {
        int cl = __ldg(&pool_cl[node]);
        int* pp = (int*)(pool_out + (size_t)cl * CC + lane * 4);
        atomicMax(pp + 0, __float_as_int(a.x));
        atomicMax(pp + 1, __float_as_int(a.y));
        atomicMax(pp + 2, __float_as_int(a.z));
        atomicMax(pp + 3, __float_as_int(a.w));
    }

    if (head_out) {
        float4 wv = ((const float4*)head_w)[lane];
        float d = a.x * wv.x + a.y * wv.y + a.z * wv.z + a.w * wv.w;
        #pragma unroll
        for (int o = 16; o; o >>= 1) d += __shfl_xor_sync(0xffffffffu, d, o);
        if (lane == 0) head_out[node] = d + head_b[0];
    }
}

// ---------------------------------------------------------------------------
// 4-channel pre-GEMM aggregation (first conv, CIN=4; stays fp32 — tiny)
// ---------------------------------------------------------------------------
__global__ void prescale4(const float* __restrict__ x, const float* __restrict__ inv,
                          float* __restrict__ p, int n) {
    int i = blockIdx.x * blockDim.x + threadIdx.x;
    if (i >= n) return;
    float s = inv[i];
    float4 v = ((const float4*)x)[i];
    v.x *= s; v.y *= s; v.z *= s; v.w *= s;
    ((float4*)p)[i] = v;
}
__global__ void csr_gather4(const int* __restrict__ rp, const int* __restrict__ esrc,
                            const float* __restrict__ p, const float* __restrict__ inv,
                            float* __restrict__ q, int n) {
    int node = blockIdx.x * blockDim.x + threadIdx.x;
    if (node >= n) return;
    int beg = __ldg(&rp[node]);
    int end = __ldg(&rp[node + 1]);
    float4 a = ((const float4*)p)[node];
    int j = beg;
    for (; j + 4 <= end; j += 4) {
        int s0 = __ldcs(&esrc[j + 0]);
        int s1 = __ldcs(&esrc[j + 1]);
        int s2 = __ldcs(&esrc[j + 2]);
        int s3 = __ldcs(&esrc[j + 3]);
        float4 v0 = ((const float4*)p)[s0];
        float4 v1 = ((const float4*)p)[s1];
        float4 v2 = ((const float4*)p)[s2];
        float4 v3 = ((const float4*)p)[s3];
        a.x += v0.x + v1.x + v2.x + v3.x;
        a.y += v0.y + v1.y + v2.y + v3.y;
        a.z += v0.z + v1.z + v2.z + v3.z;
        a.w += v0.w + v1.w + v2.w + v3.w;
    }
    for (; j < end; ++j) {
        int s = __ldcs(&esrc[j]);
        float4 v = ((const float4*)p)[s];
        a.x += v.x; a.y += v.y; a.z += v.z; a.w += v.w;
    }
    float s = __ldg(&inv[node]);
    a.x *= s; a.y *= s; a.z *= s; a.w *= s;
    ((float4*)q)[node] = a;
}

// ---------------------------------------------------------------------------
// Host-side orchestration
// ---------------------------------------------------------------------------
static void build_csr(const int* src, const int* dst, int E, int n,
                      int* fill, int* rp, int* esrc, float* inv, int* bsum)
{
    zero_i<<<(n + 255) / 256, 256>>>(fill, n);
    deg_count<<<(E + 255) / 256, 256>>>(dst, fill, E);
    inv_from_cnt<<<(n + 255) / 256, 256>>>(fill, inv, n);
    int nb = (n + 1023) / 1024;
    scan_block<<<nb, 1024>>>(fill, rp, bsum, n);
    scan_sums<<<1, 256>>>(bsum, nb);
    scan_add<<<(n + 255) / 256, 256>>>(bsum, rp, n);
    zero_i<<<(n + 255) / 256, 256>>>(fill, n);
    csr_fill<<<(E + 255) / 256, 256>>>(src, dst, rp, fill, esrc, E);
}

static void run_gcn(const float* xa, const int* gather, int Ka,
                    const float* xb, int Kb,
                    const float* W, const float* bias, const float* inv,
                    const int* rp, const int* esrc,
                    __half* g, float* y, int n,
                    const int* pool_cl = nullptr, float* pool_out = nullptr,
                    const float* head_w = nullptr, const float* head_b = nullptr,
                    float* head_out = nullptr)
{
    gcn_gemm<<<(n + 127) / 128, 256>>>(xa, gather, Ka, xb, Kb, W, inv,
                                       nullptr, 0, nullptr, g, n);
    csr_gather_relu<<<(n * 32 + 255) / 256, 256>>>(rp, esrc, g, inv, bias, y,
                                                   pool_cl, pool_out,
                                                   head_w, head_b, head_out, n);
}

extern "C" void kernel_launch(void* const* d_in, const int* in_sizes, int n_in,
                              void* d_out, int out_size)
{
    const float* x   = (const float*)d_in[0];
    const int*   ei0 = (const int*)d_in[1];
    const int*   ei1 = (const int*)d_in[2];
    const int*   ei2 = (const int*)d_in[3];
    const int*   cl0 = (const int*)d_in[4];
    const int*   cl1 = (const int*)d_in[5];
    const float* w_e0a = (const float*)d_in[6];  const float* b_e0a = (const float*)d_in[7];
    const float* w_e0b = (const float*)d_in[8];  const float* b_e0b = (const float*)d_in[9];
    const float* w_e1a = (const float*)d_in[10]; const float* b_e1a = (const float*)d_in[11];
    const float* w_e1b = (const float*)d_in[12]; const float* b_e1b = (const float*)d_in[13];
    const float* w_ba  = (const float*)d_in[14]; const float* b_ba  = (const float*)d_in[15];
    const float* w_bb  = (const float*)d_in[16]; const float* b_bb  = (const float*)d_in[17];
    const float* w_d1a = (const float*)d_in[18]; const float* b_d1a = (const float*)d_in[19];
    const float* w_d1b = (const float*)d_in[20]; const float* b_d1b = (const float*)d_in[21];
    const float* w_d0a = (const float*)d_in[22]; const float* b_d0a = (const float*)d_in[23];
    const float* w_d0b = (const float*)d_in[24]; const float* b_d0b = (const float*)d_in[25];
    const float* w_out = (const float*)d_in[26]; const float* b_out = (const float*)d_in[27];

    const int n0 = in_sizes[0] / 4;
    const int E0 = in_sizes[1] / 2;
    const int E1 = in_sizes[2] / 2;
    const int E2 = in_sizes[3] / 2;
    const int n1 = in_sizes[5];
    const int n2 = 12500;

    const int *src0 = ei0, *dst0 = ei0 + E0;
    const int *src1 = ei1, *dst1 = ei1 + E1;
    const int *src2 = ei2, *dst2 = ei2 + E2;

    float* base = nullptr;
    cudaGetSymbolAddress((void**)&base, g_scratch);

    __half* g0 = (__half*)(base + OFF_G0);
    __half* g1 = (__half*)(base + OFF_G1);
    __half* g2 = (__half*)(base + OFF_G2);
    float* t0 = base + OFF_T0; float* e0 = base + OFF_E0;
    float* t1 = base + OFF_T1; float* e1 = base + OFF_E1;
    float* x1 = base + OFF_X1;
    float* t2 = base + OFF_T2; float* x2 = base + OFF_X2;
    float* inv0 = base + OFF_INV0; float* inv1 = base + OFF_INV1; float* inv2 = base + OFF_INV2;
    int* rp0 = (int*)(base + OFF_RP0); int* fill0 = (int*)(base + OFF_FILL0);
    int* rp1 = (int*)(base + OFF_RP1); int* fill1 = (int*)(base + OFF_FILL1);
    int* rp2 = (int*)(base + OFF_RP2); int* fill2 = (int*)(base + OFF_FILL2);
    int* es0 = (int*)(base + OFF_ESRC0);
    int* es1 = (int*)(base + OFF_ESRC1);
    int* es2 = (int*)(base + OFF_ESRC2);
    int* bsum = (int*)(base + OFF_BSUM);
    float* p4 = base + OFF_G0;            // 4-ch fp32 buffers live in g0 region
    float* q4 = base + OFF_G0 + 1600000;  // (g0 unused during conv e0a)

    // --- build dst-sorted CSR + inv degree factors per level ---
    build_csr(src0, dst0, E0, n0, fill0, rp0, es0, inv0, bsum);
    build_csr(src1, dst1, E1, n1, fill1, rp1, es1, inv1, bsum);
    build_csr(src2, dst2, E2, n2, fill2, rp2, es2, inv2, bsum);

    // --- encoder level 0 (conv a: aggregate 4-ch first, then GEMM -> fp32 t0) ---
    prescale4<<<(n0 + 255) / 256, 256>>>(x, inv0, p4, n0);
    csr_gather4<<<(n0 + 255) / 256, 256>>>(rp0, es0, p4, inv0, q4, n0);
    gcn_gemm<<<(n0 + 127) / 128, 256>>>(q4, nullptr, 4, nullptr, 0, w_e0a,
                                        nullptr, b_e0a, 1, t0, nullptr, n0);
    // conv e0b with fused pool -> x1
    zero_f<<<(n1 * 128 + 255) / 256, 256>>>(x1, n1 * 128);
    run_gcn(t0, nullptr, 128, nullptr, 0, w_e0b, b_e0b, inv0, rp0, es0, g0, e0, n0,
            cl0, x1);

    // --- encoder level 1 ---
    run_gcn(x1, nullptr, 128, nullptr, 0, w_e1a, b_e1a, inv1, rp1, es1, g1, t1, n1);
    // conv e1b with fused pool -> x2
    zero_f<<<(n2 * 128 + 255) / 256, 256>>>(x2, n2 * 128);
    run_gcn(t1, nullptr, 128, nullptr, 0, w_e1b, b_e1b, inv1, rp1, es1, g1, e1, n1,
            cl1, x2);

    // --- bottom level 2 ---
    run_gcn(x2, nullptr, 128, nullptr, 0, w_ba, b_ba, inv2, rp2, es2, g2, t2, n2);
    run_gcn(t2, nullptr, 128, nullptr, 0, w_bb, b_bb, inv2, rp2, es2, g2, x2, n2);

    // --- decoder level 1: u1 = [bt[clusters1], e1] ---
    run_gcn(x2, cl1, 128, e1, 128, w_d1a, b_d1a, inv1, rp1, es1, g1, t1, n1);
    run_gcn(t1, nullptr, 128, nullptr, 0, w_d1b, b_d1b, inv1, rp1, es1, g1, x1, n1);

    // --- decoder level 0: u0 = [dl1[clusters0], e0] ---
    run_gcn(x1, cl0, 128, e0, 128, w_d0a, b_d0a, inv0, rp0, es0, g0, t0, n0);
    // final conv with fused output head (no y store at all)
    run_gcn(t0, nullptr, 128, nullptr, 0, w_d0b, b_d0b, inv0, rp0, es0, g0,
            nullptr, n0, nullptr, nullptr, w_out, b_out, (float*)d_out);
}

// round 12
// speedup vs baseline: 1.1610x; 1.1610x over previous
#include <cuda_runtime.h>
#include <cstdint>

#define CC 128  // channel width
#define XS 36   // padded Xs row stride for f32x2 GEMM

// ---------------------------------------------------------------------------
// Static scratch (no allocations allowed). Offsets in floats/ints.
// N0=200000, N1=50000, N2=12500; E0=3.2M, E1=800K, E2=200K. Row = 128 floats.
// ---------------------------------------------------------------------------
__device__ float g_scratch[112600000];  // ~450 MB

#define OFF_G0     0UL
#define OFF_T0     25600000UL
#define OFF_E0     51200000UL
#define OFF_G1     76800000UL
#define OFF_T1     83200000UL
#define OFF_E1     89600000UL
#define OFF_X1     96000000UL
#define OFF_G2     102400000UL
#define OFF_T2     104000000UL
#define OFF_X2     105600000UL
#define OFF_INV0   107200000UL
#define OFF_INV1   107400000UL
#define OFF_INV2   107450000UL
#define OFF_RP0    107500000UL
#define OFF_FILL0  107750000UL
#define OFF_RP1    107950000UL
#define OFF_FILL1  108010000UL
#define OFF_RP2    108060000UL
#define OFF_FILL2  108075000UL
#define OFF_ESRC0  108090000UL
#define OFF_ESRC1  111290000UL
#define OFF_ESRC2  112090000UL
#define OFF_BSUM   112400000UL   // 768 ints (256 per level)

// ---------------------------------------------------------------------------
// f32x2 packed-math helpers
// ---------------------------------------------------------------------------
__device__ __forceinline__ void fma2(unsigned long long& d,
                                     unsigned long long a, unsigned long long b) {
    asm("fma.rn.f32x2 %0, %1, %2, %0;" : "+l"(d) : "l"(a), "l"(b));
}
__device__ __forceinline__ unsigned long long bcast2(float x) {
    unsigned long long r;
    asm("mov.b64 %0, {%1, %1};" : "=l"(r) : "f"(x));
    return r;
}
union U64F2 { unsigned long long u; float2 f; };

// ---------------------------------------------------------------------------
// Segmented (3-level) setup kernels — one launch per stage for all levels.
// ---------------------------------------------------------------------------
__global__ void zero_f(float* __restrict__ p, int n) {
    int i = blockIdx.x * blockDim.x + threadIdx.x;
    if (i < n) p[i] = 0.0f;
}

__global__ void zero3_i(int* __restrict__ p0, int n0, int* __restrict__ p1, int n1,
                        int* __restrict__ p2, int n2) {
    int i = blockIdx.x * blockDim.x + threadIdx.x;
    if (i < n0) p0[i] = 0;
    else if (i < n0 + n1) p1[i - n0] = 0;
    else if (i < n0 + n1 + n2) p2[i - n0 - n1] = 0;
}

__global__ void deg3_count(const int* __restrict__ d0, int E0,
                           const int* __restrict__ d1, int E1,
                           const int* __restrict__ d2, int E2,
                           int* __restrict__ c0, int* __restrict__ c1,
                           int* __restrict__ c2) {
    int i = blockIdx.x * blockDim.x + threadIdx.x;
    if (i < E0) atomicAdd(&c0[d0[i]], 1);
    else if (i < E0 + E1) atomicAdd(&c1[d1[i - E0]], 1);
    else if (i < E0 + E1 + E2) atomicAdd(&c2[d2[i - E0 - E1]], 1);
}

__global__ void inv3(const int* __restrict__ c0, float* __restrict__ v0, int n0,
                     const int* __restrict__ c1, float* __restrict__ v1, int n1,
                     const int* __restrict__ c2, float* __restrict__ v2, int n2) {
    int i = blockIdx.x * blockDim.x + threadIdx.x;
    if (i < n0) v0[i] = rsqrtf((float)(c0[i] + 1));
    else if (i < n0 + n1) { int j = i - n0; v1[j] = rsqrtf((float)(c1[j] + 1)); }
    else if (i < n0 + n1 + n2) { int j = i - n0 - n1; v2[j] = rsqrtf((float)(c2[j] + 1)); }
}

// Per-block inclusive scan into rp[i+1]; zeros cnt after reading (fill reuse);
// emits block totals into per-level bsum segments (256 ints apart).
__global__ void scan3_block(int* __restrict__ c0, int* __restrict__ rp0, int n0, int nb0,
                            int* __restrict__ c1, int* __restrict__ rp1, int n1, int nb1,
                            int* __restrict__ c2, int* __restrict__ rp2, int n2, int nb2,
                            int* __restrict__ bsum) {
    __shared__ int wsums[32];
    int b = blockIdx.x;
    int* cnt; int* rp; int n; int lb; int* bs; int nb;
    if (b < nb0)            { cnt = c0; rp = rp0; n = n0; lb = b;             bs = bsum;       nb = nb0; }
    else if (b < nb0 + nb1) { cnt = c1; rp = rp1; n = n1; lb = b - nb0;       bs = bsum + 256; nb = nb1; }
    else                    { cnt = c2; rp = rp2; n = n2; lb = b - nb0 - nb1; bs = bsum + 512; nb = nb2; }

    const int t = threadIdx.x;
    int i = lb * 1024 + t;
    int v = (i < n) ? cnt[i] : 0;
    if (i < n) cnt[i] = 0;          // re-zero fill for csr_fill pass
    int x = v;
    #pragma unroll
    for (int o = 1; o < 32; o <<= 1) {
        int y = __shfl_up_sync(0xffffffffu, x, o);
        if ((t & 31) >= o) x += y;
    }
    if ((t & 31) == 31) wsums[t >> 5] = x;
    __syncthreads();
    if (t < 32) {
        int w = wsums[t];
        #pragma unroll
        for (int o = 1; o < 32; o <<= 1) {
            int y = __shfl_up_sync(0xffffffffu, w, o);
            if (t >= o) w += y;
        }
        wsums[t] = w;
    }
    __syncthreads();
    int incl = x + ((t >= 32) ? wsums[(t >> 5) - 1] : 0);
    if (i < n) rp[i + 1] = incl;
    if (t == 1023) bs[lb] = incl;
}

// Exclusive scan of each level's block sums (3 blocks, 256 threads each).
__global__ void scan3_sums(int* __restrict__ bsum, int nb0, int nb1, int nb2) {
    __shared__ int wsums[8];
    int* bs = bsum + 256 * blockIdx.x;
    int nb = (blockIdx.x == 0) ? nb0 : (blockIdx.x == 1) ? nb1 : nb2;
    const int t = threadIdx.x;
    int v = (t < nb) ? bs[t] : 0;
    int x = v;
    #pragma unroll
    for (int o = 1; o < 32; o <<= 1) {
        int y = __shfl_up_sync(0xffffffffu, x, o);
        if ((t & 31) >= o) x += y;
    }
    if ((t & 31) == 31) wsums[t >> 5] = x;
    __syncthreads();
    if (t < 32) {
        int w = (t < 8) ? wsums[t] : 0;
        #pragma unroll
        for (int o = 1; o < 8; o <<= 1) {
            int y = __shfl_up_sync(0xffffffffu, w, o);
            if (t >= o) w += y;
        }
        if (t < 8) wsums[t] = w;
    }
    __syncthreads();
    int incl = x + ((t >= 32) ? wsums[(t >> 5) - 1] : 0);
    if (t < nb) bs[t] = incl - v;
}

__global__ void scan3_add(const int* __restrict__ bsum,
                          int* __restrict__ rp0, int n0,
                          int* __restrict__ rp1, int n1,
                          int* __restrict__ rp2, int n2) {
    int i = blockIdx.x * blockDim.x + threadIdx.x;
    if (i == 0) { rp0[0] = 0; rp1[0] = 0; rp2[0] = 0; }
    if (i < n0) rp0[i + 1] += bsum[i >> 10];
    else if (i < n0 + n1) { int j = i - n0; rp1[j + 1] += bsum[256 + (j >> 10)]; }
    else if (i < n0 + n1 + n2) { int j = i - n0 - n1; rp2[j + 1] += bsum[512 + (j >> 10)]; }
}

__global__ void csr3_fill(const int* __restrict__ s0, const int* __restrict__ d0, int E0,
                          const int* __restrict__ s1, const int* __restrict__ d1, int E1,
                          const int* __restrict__ s2, const int* __restrict__ d2, int E2,
                          const int* __restrict__ rp0, int* __restrict__ f0, int* __restrict__ e0,
                          const int* __restrict__ rp1, int* __restrict__ f1, int* __restrict__ e1,
                          const int* __restrict__ rp2, int* __restrict__ f2, int* __restrict__ e2) {
    int i = blockIdx.x * blockDim.x + threadIdx.x;
    const int *src, *dst, *rp; int* fill; int* esrc; int e;
    if (i < E0)            { src = s0; dst = d0; rp = rp0; fill = f0; esrc = e0; e = i; }
    else if (i < E0 + E1)  { src = s1; dst = d1; rp = rp1; fill = f1; esrc = e1; e = i - E0; }
    else if (i < E0 + E1 + E2) { src = s2; dst = d2; rp = rp2; fill = f2; esrc = e2; e = i - E0 - E1; }
    else return;
    int d = dst[e];
    int pos = rp[d] + atomicAdd(&fill[d], 1);
    esrc[pos] = src[e];
}

// ---------------------------------------------------------------------------
// f32x2 GEMM (R3-proven data path; launch_bounds caps regs at 128 so 2 blocks
// co-reside per SM -> 4 warps/SMSP to hide LDS latency between FFMA2 bursts):
//   g[i][c] = epi( sum_k X(i,k) * W[k][c] )
//   X(i,k) = (k < Ka) ? xa[(gatherA ? gatherA[i] : i)][k] : xb[i][k-Ka]
//   epi: * inv[i] if inv; + bias[c], relu if requested.
// Tile: 128 rows x 128 cols, 256 threads. Thread = 8 rows x 8 cols (4 pairs).
// ---------------------------------------------------------------------------
__global__ void __launch_bounds__(256, 2)
gcn_gemm(const float* __restrict__ xa, const int* __restrict__ gatherA, int Ka,
         const float* __restrict__ xb, int Kb,
         const float* __restrict__ W, const float* __restrict__ inv,
         const float* __restrict__ bias, int do_relu,
         float* __restrict__ g, int n)
{
    __shared__ float Ws[32 * CC];    // 16 KB
    __shared__ float Xs[128 * XS];   // 18 KB
    const int K = Ka + Kb;
    const int tid = threadIdx.x;
    const int cg = tid & 15;         // 8-col group
    const int rg = tid >> 4;         // 0..15; rows rg + 16*i
    const int row0 = blockIdx.x * 128;

    unsigned long long acc[8][4];
    #pragma unroll
    for (int i = 0; i < 8; ++i)
        #pragma unroll
        for (int j = 0; j < 4; ++j) acc[i][j] = 0ULL;

    for (int kk = 0; kk < K; kk += 32) {
        int kc = K - kk; if (kc > 32) kc = 32;
        const int kc4 = kc >> 2;
        for (int idx = tid; idx < kc * 32; idx += 256) {
            int k = idx >> 5, c4 = idx & 31;
            ((float4*)Ws)[k * 32 + c4] = ((const float4*)(W + (size_t)(kk + k) * CC))[c4];
        }
        for (int idx = tid; idx < 128 * kc4; idx += 256) {
            int r = idx / kc4, k4 = idx - r * kc4;
            int row = row0 + r;
            float4 v = make_float4(0.f, 0.f, 0.f, 0.f);
            if (row < n) {
                int kg = kk + k4 * 4;
                if (kg < Ka) {
                    int ra = gatherA ? __ldg(&gatherA[row]) : row;
                    v = *(const float4*)(xa + (size_t)ra * Ka + kg);
                } else {
                    v = *(const float4*)(xb + (size_t)row * Kb + (kg - Ka));
                }
            }
            *(float4*)(Xs + r * XS + k4 * 4) = v;
        }
        __syncthreads();
        for (int k4 = 0; k4 < kc4; ++k4) {
            float4 xv[8];
            #pragma unroll
            for (int i = 0; i < 8; ++i)
                xv[i] = *(const float4*)(Xs + (rg + 16 * i) * XS + k4 * 4);
            #pragma unroll
            for (int k = 0; k < 4; ++k) {
                const float* wrow = Ws + (k4 * 4 + k) * CC + cg * 8;
                ulonglong2 w01 = *(const ulonglong2*)(wrow);
                ulonglong2 w23 = *(const ulonglong2*)(wrow + 4);
                #pragma unroll
                for (int i = 0; i < 8; ++i) {
                    float xs = (k == 0) ? xv[i].x : (k == 1) ? xv[i].y
                             : (k == 2) ? xv[i].z : xv[i].w;
                    unsigned long long xb2 = bcast2(xs);
                    fma2(acc[i][0], xb2, w01.x);
                    fma2(acc[i][1], xb2, w01.y);
                    fma2(acc[i][2], xb2, w23.x);
                    fma2(acc[i][3], xb2, w23.y);
                }
            }
        }
        __syncthreads();
    }
    #pragma unroll
    for (int i = 0; i < 8; ++i) {
        int row = row0 + rg + 16 * i;
        if (row >= n) continue;
        float s = inv ? inv[row] : 1.0f;
        U64F2 p0, p1, p2, p3;
        p0.u = acc[i][0]; p1.u = acc[i][1]; p2.u = acc[i][2]; p3.u = acc[i][3];
        float4 v0 = make_float4(p0.f.x * s, p0.f.y * s, p1.f.x * s, p1.f.y * s);
        float4 v1 = make_float4(p2.f.x * s, p2.f.y * s, p3.f.x * s, p3.f.y * s);
        if (bias) {
            float4 b0 = *(const float4*)(bias + cg * 8);
            float4 b1 = *(const float4*)(bias + cg * 8 + 4);
            v0.x += b0.x; v0.y += b0.y; v0.z += b0.z; v0.w += b0.w;
            v1.x += b1.x; v1.y += b1.y; v1.z += b1.z; v1.w += b1.w;
        }
        if (do_relu) {
            v0.x = fmaxf(v0.x, 0.f); v0.y = fmaxf(v0.y, 0.f);
            v0.z = fmaxf(v0.z, 0.f); v0.w = fmaxf(v0.w, 0.f);
            v1.x = fmaxf(v1.x, 0.f); v1.y = fmaxf(v1.y, 0.f);
            v1.z = fmaxf(v1.z, 0.f); v1.w = fmaxf(v1.w, 0.f);
        }
        float* op = g + (size_t)row * CC + cg * 8;
        *(float4*)(op) = v0;
        *(float4*)(op + 4) = v1;
    }
}

// ---------------------------------------------------------------------------
// CSR gather + finalize (+ optional fused max-pool and/or fused output head):
//   a = relu(inv[d] * (g[d] + sum_{e: dst=d} g[src[e]]) + bias)
// fp32 g; one warp per node; float4 per lane; 8-deep MLP unroll.
// Edge list via __ldcs (read-once per conv; keep L2 for g rows).
// ---------------------------------------------------------------------------
__global__ void csr_gather_relu(const int* __restrict__ rp, const int* __restrict__ esrc,
                                const float* __restrict__ g, const float* __restrict__ inv,
                                const float* __restrict__ bias, float* __restrict__ y,
                                const int* __restrict__ pool_cl, float* __restrict__ pool_out,
                                const float* __restrict__ head_w, const float* __restrict__ head_b,
                                float* __restrict__ head_out, int n)
{
    int node = (blockIdx.x * blockDim.x + threadIdx.x) >> 5;
    int lane = threadIdx.x & 31;
    if (node >= n) return;
    int beg = __ldg(&rp[node]);
    int end = __ldg(&rp[node + 1]);

    float4 a = ((const float4*)(g + (size_t)node * CC))[lane];  // self loop
    int j = beg;
    for (; j + 8 <= end; j += 8) {
        int s0 = __ldcs(&esrc[j + 0]);
        int s1 = __ldcs(&esrc[j + 1]);
        int s2 = __ldcs(&esrc[j + 2]);
        int s3 = __ldcs(&esrc[j + 3]);
        int s4 = __ldcs(&esrc[j + 4]);
        int s5 = __ldcs(&esrc[j + 5]);
        int s6 = __ldcs(&esrc[j + 6]);
        int s7 = __ldcs(&esrc[j + 7]);
        float4 v0 = ((const float4*)(g + (size_t)s0 * CC))[lane];
        float4 v1 = ((const float4*)(g + (size_t)s1 * CC))[lane];
        float4 v2 = ((const float4*)(g + (size_t)s2 * CC))[lane];
        float4 v3 = ((const float4*)(g + (size_t)s3 * CC))[lane];
        float4 v4 = ((const float4*)(g + (size_t)s4 * CC))[lane];
        float4 v5 = ((const float4*)(g + (size_t)s5 * CC))[lane];
        float4 v6 = ((const float4*)(g + (size_t)s6 * CC))[lane];
        float4 v7 = ((const float4*)(g + (size_t)s7 * CC))[lane];
        a.x += (v0.x + v1.x) + (v2.x + v3.x) + (v4.x + v5.x) + (v6.x + v7.x);
        a.y += (v0.y + v1.y) + (v2.y + v3.y) + (v4.y + v5.y) + (v6.y + v7.y);
        a.z += (v0.z + v1.z) + (v2.z + v3.z) + (v4.z + v5.z) + (v6.z + v7.z);
        a.w += (v0.w + v1.w) + (v2.w + v3.w) + (v4.w + v5.w) + (v6.w + v7.w);
    }
    for (; j < end; ++j) {
        int s = __ldcs(&esrc[j]);
        float4 v = ((const float4*)(g + (size_t)s * CC))[lane];
        a.x += v.x; a.y += v.y; a.z += v.z; a.w += v.w;
    }
    float s = __ldg(&inv[node]);
    float4 b = ((const float4*)bias)[lane];
    a.x = fmaxf(a.x * s + b.x, 0.f);
    a.y = fmaxf(a.y * s + b.y, 0.f);
    a.z = fmaxf(a.z * s + b.z, 0.f);
    a.w = fmaxf(a.w * s + b.w, 0.f);

    if (y) ((float4*)(y + (size_t)node * CC))[lane] = a;

    if (pool_out) {
        int cl = __ldg(&pool_cl[node]);
        int* pp = (int*)(pool_out + (size_t)cl * CC + lane * 4);
        atomicMax(pp + 0, __float_as_int(a.x));
        atomicMax(pp + 1, __float_as_int(a.y));
        atomicMax(pp + 2, __float_as_int(a.z));
        atomicMax(pp + 3, __float_as_int(a.w));
    }

    if (head_out) {
        float4 wv = ((const float4*)head_w)[lane];
        float d = a.x * wv.x + a.y * wv.y + a.z * wv.z + a.w * wv.w;
        #pragma unroll
        for (int o = 16; o; o >>= 1) d += __shfl_xor_sync(0xffffffffu, d, o);
        if (lane == 0) head_out[node] = d + head_b[0];
    }
}

// ---------------------------------------------------------------------------
// 4-channel pre-GEMM aggregation (first conv, CIN=4)
// ---------------------------------------------------------------------------
__global__ void prescale4(const float* __restrict__ x, const float* __restrict__ inv,
                          float* __restrict__ p, int n) {
    int i = blockIdx.x * blockDim.x + threadIdx.x;
    if (i >= n) return;
    float s = inv[i];
    float4 v = ((const float4*)x)[i];
    v.x *= s; v.y *= s; v.z *= s; v.w *= s;
    ((float4*)p)[i] = v;
}
__global__ void csr_gather4(const int* __restrict__ rp, const int* __restrict__ esrc,
                            const float* __restrict__ p, const float* __restrict__ inv,
                            float* __restrict__ q, int n) {
    int node = blockIdx.x * blockDim.x + threadIdx.x;
    if (node >= n) return;
    int beg = __ldg(&rp[node]);
    int end = __ldg(&rp[node + 1]);
    float4 a = ((const float4*)p)[node];
    int j = beg;
    for (; j + 4 <= end; j += 4) {
        int s0 = __ldcs(&esrc[j + 0]);
        int s1 = __ldcs(&esrc[j + 1]);
        int s2 = __ldcs(&esrc[j + 2]);
        int s3 = __ldcs(&esrc[j + 3]);
        float4 v0 = ((const float4*)p)[s0];
        float4 v1 = ((const float4*)p)[s1];
        float4 v2 = ((const float4*)p)[s2];
        float4 v3 = ((const float4*)p)[s3];
        a.x += v0.x + v1.x + v2.x + v3.x;
        a.y += v0.y + v1.y + v2.y + v3.y;
        a.z += v0.z + v1.z + v2.z + v3.z;
        a.w += v0.w + v1.w + v2.w + v3.w;
    }
    for (; j < end; ++j) {
        int s = __ldcs(&esrc[j]);
        float4 v = ((const float4*)p)[s];
        a.x += v.x; a.y += v.y; a.z += v.z; a.w += v.w;
    }
    float s = __ldg(&inv[node]);
    a.x *= s; a.y *= s; a.z *= s; a.w *= s;
    ((float4*)q)[node] = a;
}

// ---------------------------------------------------------------------------
// Host-side orchestration
// ---------------------------------------------------------------------------
static void run_gcn(const float* xa, const int* gather, int Ka,
                    const float* xb, int Kb,
                    const float* W, const float* bias, const float* inv,
                    const int* rp, const int* esrc,
                    float* g, float* y, int n,
                    const int* pool_cl = nullptr, float* pool_out = nullptr,
                    const float* head_w = nullptr, const float* head_b = nullptr,
                    float* head_out = nullptr)
{
    gcn_gemm<<<(n + 127) / 128, 256>>>(xa, gather, Ka, xb, Kb, W, inv,
                                       nullptr, 0, g, n);
    csr_gather_relu<<<(n * 32 + 255) / 256, 256>>>(rp, esrc, g, inv, bias, y,
                                                   pool_cl, pool_out,
                                                   head_w, head_b, head_out, n);
}

extern "C" void kernel_launch(void* const* d_in, const int* in_sizes, int n_in,
                              void* d_out, int out_size)
{
    const float* x   = (const float*)d_in[0];
    const int*   ei0 = (const int*)d_in[1];
    const int*   ei1 = (const int*)d_in[2];
    const int*   ei2 = (const int*)d_in[3];
    const int*   cl0 = (const int*)d_in[4];
    const int*   cl1 = (const int*)d_in[5];
    const float* w_e0a = (const float*)d_in[6];  const float* b_e0a = (const float*)d_in[7];
    const float* w_e0b = (const float*)d_in[8];  const float* b_e0b = (const float*)d_in[9];
    const float* w_e1a = (const float*)d_in[10]; const float* b_e1a = (const float*)d_in[11];
    const float* w_e1b = (const float*)d_in[12]; const float* b_e1b = (const float*)d_in[13];
    const float* w_ba  = (const float*)d_in[14]; const float* b_ba  = (const float*)d_in[15];
    const float* w_bb  = (const float*)d_in[16]; const float* b_bb  = (const float*)d_in[17];
    const float* w_d1a = (const float*)d_in[18]; const float* b_d1a = (const float*)d_in[19];
    const float* w_d1b = (const float*)d_in[20]; const float* b_d1b = (const float*)d_in[21];
    const float* w_d0a = (const float*)d_in[22]; const float* b_d0a = (const float*)d_in[23];
    const float* w_d0b = (const float*)d_in[24]; const float* b_d0b = (const float*)d_in[25];
    const float* w_out = (const float*)d_in[26]; const float* b_out = (const float*)d_in[27];

    const int n0 = in_sizes[0] / 4;
    const int E0 = in_sizes[1] / 2;
    const int E1 = in_sizes[2] / 2;
    const int E2 = in_sizes[3] / 2;
    const int n1 = in_sizes[5];
    const int n2 = 12500;

    const int *src0 = ei0, *dst0 = ei0 + E0;
    const int *src1 = ei1, *dst1 = ei1 + E1;
    const int *src2 = ei2, *dst2 = ei2 + E2;

    float* base = nullptr;
    cudaGetSymbolAddress((void**)&base, g_scratch);

    float* g0 = base + OFF_G0; float* t0 = base + OFF_T0; float* e0 = base + OFF_E0;
    float* g1 = base + OFF_G1; float* t1 = base + OFF_T1; float* e1 = base + OFF_E1;
    float* x1 = base + OFF_X1;
    float* g2 = base + OFF_G2; float* t2 = base + OFF_T2; float* x2 = base + OFF_X2;
    float* inv0 = base + OFF_INV0; float* inv1 = base + OFF_INV1; float* inv2 = base + OFF_INV2;
    int* rp0 = (int*)(base + OFF_RP0); int* fill0 = (int*)(base + OFF_FILL0);
    int* rp1 = (int*)(base + OFF_RP1); int* fill1 = (int*)(base + OFF_FILL1);
    int* rp2 = (int*)(base + OFF_RP2); int* fill2 = (int*)(base + OFF_FILL2);
    int* es0 = (int*)(base + OFF_ESRC0);
    int* es1 = (int*)(base + OFF_ESRC1);
    int* es2 = (int*)(base + OFF_ESRC2);
    int* bsum = (int*)(base + OFF_BSUM);
    float* p4 = base + OFF_G0;            // 4-ch buffers live in g0 region
    float* q4 = base + OFF_G0 + 1600000;  // (g0 unused during conv e0a)

    // --- build dst-sorted CSR + inv degree factors, all 3 levels batched ---
    const int nN = n0 + n1 + n2;
    const int nE = E0 + E1 + E2;
    const int nb0 = (n0 + 1023) / 1024, nb1 = (n1 + 1023) / 1024, nb2 = (n2 + 1023) / 1024;
    zero3_i<<<(nN + 255) / 256, 256>>>(fill0, n0, fill1, n1, fill2, n2);
    deg3_count<<<(nE + 255) / 256, 256>>>(dst0, E0, dst1, E1, dst2, E2,
                                          fill0, fill1, fill2);
    inv3<<<(nN + 255) / 256, 256>>>(fill0, inv0, n0, fill1, inv1, n1, fill2, inv2, n2);
    scan3_block<<<nb0 + nb1 + nb2, 1024>>>(fill0, rp0, n0, nb0,
                                           fill1, rp1, n1, nb1,
                                           fill2, rp2, n2, nb2, bsum);
    scan3_sums<<<3, 256>>>(bsum, nb0, nb1, nb2);
    scan3_add<<<(nN + 255) / 256, 256>>>(bsum, rp0, n0, rp1, n1, rp2, n2);
    csr3_fill<<<(nE + 255) / 256, 256>>>(src0, dst0, E0, src1, dst1, E1, src2, dst2, E2,
                                         rp0, fill0, es0, rp1, fill1, es1, rp2, fill2, es2);

    // --- encoder level 0 (conv a: aggregate 4-ch first, then GEMM) ---
    prescale4<<<(n0 + 255) / 256, 256>>>(x, inv0, p4, n0);
    csr_gather4<<<(n0 + 255) / 256, 256>>>(rp0, es0, p4, inv0, q4, n0);
    gcn_gemm<<<(n0 + 127) / 128, 256>>>(q4, nullptr, 4, nullptr, 0, w_e0a,
                                        nullptr, b_e0a, 1, t0, n0);
    // conv e0b with fused pool -> x1
    zero_f<<<(n1 * 128 + 255) / 256, 256>>>(x1, n1 * 128);
    run_gcn(t0, nullptr, 128, nullptr, 0, w_e0b, b_e0b, inv0, rp0, es0, g0, e0, n0,
            cl0, x1);

    // --- encoder level 1 ---
    run_gcn(x1, nullptr, 128, nullptr, 0, w_e1a, b_e1a, inv1, rp1, es1, g1, t1, n1);
    // conv e1b with fused pool -> x2
    zero_f<<<(n2 * 128 + 255) / 256, 256>>>(x2, n2 * 128);
    run_gcn(t1, nullptr, 128, nullptr, 0, w_e1b, b_e1b, inv1, rp1, es1, g1, e1, n1,
            cl1, x2);

    // --- bottom level 2 ---
    run_gcn(x2, nullptr, 128, nullptr, 0, w_ba, b_ba, inv2, rp2, es2, g2, t2, n2);
    run_gcn(t2, nullptr, 128, nullptr, 0, w_bb, b_bb, inv2, rp2, es2, g2, x2, n2);

    // --- decoder level 1: u1 = [bt[clusters1], e1] ---
    run_gcn(x2, cl1, 128, e1, 128, w_d1a, b_d1a, inv1, rp1, es1, g1, t1, n1);
    run_gcn(t1, nullptr, 128, nullptr, 0, w_d1b, b_d1b, inv1, rp1, es1, g1, x1, n1);

    // --- decoder level 0: u0 = [dl1[clusters0], e0] ---
    run_gcn(x1, cl0, 128, e0, 128, w_d0a, b_d0a, inv0, rp0, es0, g0, t0, n0);
    // final conv with fused output head (no y store at all)
    run_gcn(t0, nullptr, 128, nullptr, 0, w_d0b, b_d0b, inv0, rp0, es0, g0,
            nullptr, n0, nullptr, nullptr, w_out, b_out, (float*)d_out);
}